// round 15
// baseline (speedup 1.0000x reference)
#include <cuda_runtime.h>
#include <cuda_fp16.h>

// ---------------------------------------------------------------------------
// CrossViewSwapAttention — fp16-MMA LN-GEMM -> fp16 q/k/v -> fp16-MMA flash
// attention (coef pre-folded into Q) -> fp16 att -> proj.
//   qf (L=64, Nq=384, d=128), kf/vf (L=64, Nk=480, d=128), heads 4 x dh 32.
// ---------------------------------------------------------------------------

#define NQ_ROWS  24576
#define NK_ROWS  30720
#define D        128

__device__ __half g_q16 [NQ_ROWS * D];
__device__ __half g_k16 [NK_ROWS * D];
__device__ __half g_v16 [NK_ROWS * D];
__device__ __half g_att16[NQ_ROWS * D];

typedef unsigned long long u64;
typedef unsigned int u32;

__device__ __forceinline__ float ex2(float x) {
    float r;
    asm("ex2.approx.f32 %0, %1;" : "=f"(r) : "f"(x));
    return r;
}
__device__ __forceinline__ void mma_f16(float c[4], const u32 a[4], u32 b0, u32 b1) {
    asm("mma.sync.aligned.m16n8k16.row.col.f32.f16.f16.f32 "
        "{%0,%1,%2,%3}, {%4,%5,%6,%7}, {%8,%9}, {%0,%1,%2,%3};"
        : "+f"(c[0]), "+f"(c[1]), "+f"(c[2]), "+f"(c[3])
        : "r"(a[0]), "r"(a[1]), "r"(a[2]), "r"(a[3]), "r"(b0), "r"(b1));
}
__device__ __forceinline__ void ldmatrix_x2_trans(u32& r0, u32& r1, const void* p) {
    u32 addr = (u32)__cvta_generic_to_shared(p);
    asm volatile("ldmatrix.sync.aligned.m8n8.x2.trans.shared.b16 {%0,%1}, [%2];"
                 : "=r"(r0), "=r"(r1) : "r"(addr));
}

// ---------------------------------------------------------------------------
// Kernel A: fused LayerNorm + fp16-MMA Linear for q,k,v; fp16 outputs.
// Q outputs pre-scaled by attn_scale * dh^-0.5 * log2e (linear fold).
//   Xs:  normalized X fp16 [64][136]   (A-frag u32 LDS banks 4g+tig: clean)
//   W_s: full W fp16      [128][136]   (ldmatrix.x2.trans rows: bank-clean)
// Single staging pass; 8 k16 MMA steps, 16 HMMA per step per warp.
// ---------------------------------------------------------------------------
#define XS_H 136
#define WS_H 136
#define LN_SMEM_BYTES ((64 * XS_H + 128 * WS_H) * 2)   // 52224 B

__global__ __launch_bounds__(128, 4)
void ln_all_kernel(const float* __restrict__ q,
                   const float* __restrict__ k,
                   const float* __restrict__ v,
                   const float* __restrict__ scale_ptr,
                   const float* __restrict__ lnq_g, const float* __restrict__ lnq_b,
                   const float* __restrict__ Wq,    const float* __restrict__ bq,
                   const float* __restrict__ lnk_g, const float* __restrict__ lnk_b,
                   const float* __restrict__ Wk,    const float* __restrict__ bk,
                   const float* __restrict__ lnv_g, const float* __restrict__ lnv_b,
                   const float* __restrict__ Wv,    const float* __restrict__ bv)
{
    extern __shared__ __half hsm[];
    __half* Xs  = hsm;               // [64][136]
    __half* W_s = hsm + 64 * XS_H;   // [128][136]

    const int bx   = blockIdx.x;
    const int tid  = threadIdx.x;
    const int warp = tid >> 5;
    const int lane = tid & 31;

    const float *x, *gamma, *beta, *W, *blin;
    __half* out16;
    int rowsPerL, perN, rbase;
    float cf = 1.0f;
    if (bx < 384) {
        x = q; gamma = lnq_g; beta = lnq_b; W = Wq; blin = bq;
        out16 = g_q16; rowsPerL = 384; perN = 64; rbase = bx * 64;
        cf = scale_ptr[0] * 0.17677669529663687f * 1.4426950408889634f;
    } else if (bx < 864) {
        x = k; gamma = lnk_g; beta = lnk_b; W = Wk; blin = bk;
        out16 = g_k16; rowsPerL = 480; perN = 80; rbase = (bx - 384) * 64;
    } else {
        x = v; gamma = lnv_g; beta = lnv_b; W = Wv; blin = bv;
        out16 = g_v16; rowsPerL = 480; perN = 80; rbase = (bx - 864) * 64;
    }

    // Phase 1: each warp normalizes 16 rows; float2 lanes, half2 stores.
    {
        const float2 gA = *(const float2*)(gamma + 2 * lane);
        const float2 gB = *(const float2*)(gamma + 2 * lane + 64);
        const float2 bA = *(const float2*)(beta + 2 * lane);
        const float2 bB = *(const float2*)(beta + 2 * lane + 64);

        #pragma unroll 4
        for (int rr = 0; rr < 16; rr++) {
            const int r   = warp * 16 + rr;
            const int row = rbase + r;
            const int L   = row / rowsPerL;
            const int N   = row - L * rowsPerL;
            const int nn  = N / perN;
            const int wi  = N - nn * perN;
            const float* xr = x + ((nn * 64 + L) * perN + wi) * D;

            const float2 va = *(const float2*)(xr + 2 * lane);
            const float2 vb = *(const float2*)(xr + 2 * lane + 64);
            float s = (va.x + va.y) + (vb.x + vb.y);
            #pragma unroll
            for (int o = 16; o; o >>= 1) s += __shfl_xor_sync(0xffffffffu, s, o);
            const float mu = s * (1.0f / 128.0f);
            const float dax = va.x - mu, day = va.y - mu;
            const float dbx = vb.x - mu, dby = vb.y - mu;
            float sq = dax * dax + day * day + dbx * dbx + dby * dby;
            #pragma unroll
            for (int o = 16; o; o >>= 1) sq += __shfl_xor_sync(0xffffffffu, sq, o);
            const float rstd = rsqrtf(sq * (1.0f / 128.0f) + 1e-5f);

            const __half2 ha = __floats2half2_rn(dax * rstd * gA.x + bA.x,
                                                 day * rstd * gA.y + bA.y);
            const __half2 hb = __floats2half2_rn(dbx * rstd * gB.x + bB.x,
                                                 dby * rstd * gB.y + bB.y);
            *(u32*)(Xs + r * XS_H + 2 * lane)      = *(const u32*)&ha;
            *(u32*)(Xs + r * XS_H + 2 * lane + 64) = *(const u32*)&hb;
        }
    }

    // Stage the FULL W (128x128) as fp16, one pass (independent of phase 1).
    #pragma unroll 8
    for (int t = 0; t < 32; t++) {
        const int idx = tid + t * 128;       // 0..4095 float4s
        const int j   = idx >> 5;
        const int c4  = idx & 31;
        const float4 f = *(const float4*)(W + j * 128 + c4 * 4);
        const __half2 h0 = __floats2half2_rn(f.x, f.y);
        const __half2 h1 = __floats2half2_rn(f.z, f.w);
        u64 pk = (u64)(*(const u32*)&h0) | ((u64)(*(const u32*)&h1) << 32);
        *(u64*)(W_s + j * WS_H + c4 * 4) = pk;
    }
    __syncthreads();

    // Phase 2: fp16 MMA. Warp (mh, nh) owns rows mh*32..+32, cols nh*64..+64.
    const int g   = lane >> 2;
    const int tig = lane & 3;
    const int mh  = warp >> 1;
    const int nh  = warp & 1;

    float acc[2][8][4];
    #pragma unroll
    for (int mt = 0; mt < 2; mt++)
        #pragma unroll
        for (int nt = 0; nt < 8; nt++)
            #pragma unroll
            for (int i = 0; i < 4; i++) acc[mt][nt][i] = 0.0f;

    #pragma unroll
    for (int ks = 0; ks < 8; ks++) {
        u32 a[2][4];
        #pragma unroll
        for (int mt = 0; mt < 2; mt++) {
            const __half* pa = Xs + (mh * 32 + mt * 16 + g) * XS_H + ks * 16 + 2 * tig;
            a[mt][0] = *(const u32*)(pa);
            a[mt][1] = *(const u32*)(pa + 8 * XS_H);
            a[mt][2] = *(const u32*)(pa + 8);
            a[mt][3] = *(const u32*)(pa + 8 * XS_H + 8);
        }
        #pragma unroll
        for (int nt = 0; nt < 8; nt++) {
            const int n0 = nh * 64 + nt * 8;
            u32 b0, b1;
            ldmatrix_x2_trans(b0, b1, W_s + (ks * 16 + (lane & 15)) * WS_H + n0);
            mma_f16(acc[0][nt], a[0], b0, b1);
            mma_f16(acc[1][nt], a[1], b0, b1);
        }
    }

    // Epilogue: + bias, (Q only) * coef, pack fp16.
    #pragma unroll
    for (int mt = 0; mt < 2; mt++) {
        const int r0 = rbase + mh * 32 + mt * 16;
        #pragma unroll
        for (int nt = 0; nt < 8; nt++) {
            const int col = nh * 64 + nt * 8 + 2 * tig;
            const float2 bb = *(const float2*)(blin + col);
            const __half2 h0 = __floats2half2_rn((acc[mt][nt][0] + bb.x) * cf,
                                                 (acc[mt][nt][1] + bb.y) * cf);
            const __half2 h1 = __floats2half2_rn((acc[mt][nt][2] + bb.x) * cf,
                                                 (acc[mt][nt][3] + bb.y) * cf);
            *(u32*)(out16 + (r0 + g)     * D + col) = *(const u32*)&h0;
            *(u32*)(out16 + (r0 + g + 8) * D + col) = *(const u32*)&h1;
        }
    }
}

// ---------------------------------------------------------------------------
// Kernel B: fp16 tensor-core flash attention (unchanged from R14 win).
// ---------------------------------------------------------------------------
#define KV_STR 40

__global__ __launch_bounds__(128, 5)
void attn_kernel(const float* __restrict__ scale_ptr)
{
    __shared__ __half Ks[96 * KV_STR];
    __shared__ __half Vs[96 * KV_STR];

    const int bx   = blockIdx.x;
    const int h    = bx & 3;
    const int l    = (bx >> 2) & 63;
    const int qt   = bx >> 8;
    const int tid  = threadIdx.x;
    const int w    = tid >> 5;
    const int lane = tid & 31;
    const int g    = lane >> 2;
    const int tig  = lane & 3;

    const __half* qbase = g_q16 + (l * 384 + qt * 128) * D + h * 32;
    const __half* kbase = g_k16 + (l * 480) * D + h * 32;
    const __half* vbase = g_v16 + (l * 480) * D + h * 32;

    u32 qa[2][2][4];
    #pragma unroll
    for (int mt = 0; mt < 2; mt++) {
        #pragma unroll
        for (int ks = 0; ks < 2; ks++) {
            const __half* p = qbase + (w * 32 + mt * 16 + g) * D + ks * 16 + 2 * tig;
            qa[mt][ks][0] = *(const u32*)(p);
            qa[mt][ks][1] = *(const u32*)(p + 8 * D);
            qa[mt][ks][2] = *(const u32*)(p + 8);
            qa[mt][ks][3] = *(const u32*)(p + 8 * D + 8);
        }
    }

    float o[2][4][4];
    #pragma unroll
    for (int mt = 0; mt < 2; mt++)
        #pragma unroll
        for (int vn = 0; vn < 4; vn++)
            #pragma unroll
            for (int i = 0; i < 4; i++) o[mt][vn][i] = 0.0f;
    float rs0[2] = {0.f, 0.f};
    float rs1[2] = {0.f, 0.f};

    for (int c0 = 0; c0 < 480; c0 += 96) {
        __syncthreads();
        #pragma unroll
        for (int t = 0; t < 3; t++) {
            const int idx = tid + t * 128;
            const int row = idx >> 2;
            const int seg = idx & 3;
            *(float4*)(Ks + row * KV_STR + seg * 8) =
                *(const float4*)(kbase + (c0 + row) * D + seg * 8);
            *(float4*)(Vs + row * KV_STR + seg * 8) =
                *(const float4*)(vbase + (c0 + row) * D + seg * 8);
        }
        __syncthreads();

        #pragma unroll
        for (int pt = 0; pt < 6; pt++) {
            float s[2][2][4];
            #pragma unroll
            for (int mt = 0; mt < 2; mt++)
                #pragma unroll
                for (int n2 = 0; n2 < 2; n2++)
                    #pragma unroll
                    for (int i = 0; i < 4; i++) s[mt][n2][i] = 0.0f;

            #pragma unroll
            for (int n2 = 0; n2 < 2; n2++) {
                const int n0 = pt * 16 + n2 * 8;
                #pragma unroll
                for (int ks = 0; ks < 2; ks++) {
                    const __half* kp = Ks + (n0 + g) * KV_STR + ks * 16 + 2 * tig;
                    const u32 b0 = *(const u32*)(kp);
                    const u32 b1 = *(const u32*)(kp + 8);
                    mma_f16(s[0][n2], qa[0][ks], b0, b1);
                    mma_f16(s[1][n2], qa[1][ks], b0, b1);
                }
            }

            u32 aP[2][4];
            #pragma unroll
            for (int mt = 0; mt < 2; mt++) {
                #pragma unroll
                for (int n2 = 0; n2 < 2; n2++) {
                    const float p0 = ex2(s[mt][n2][0]);
                    const float p1 = ex2(s[mt][n2][1]);
                    const float p2 = ex2(s[mt][n2][2]);
                    const float p3 = ex2(s[mt][n2][3]);
                    rs0[mt] += p0 + p1;
                    rs1[mt] += p2 + p3;
                    const __half2 h01 = __floats2half2_rn(p0, p1);
                    const __half2 h23 = __floats2half2_rn(p2, p3);
                    aP[mt][n2 * 2 + 0] = *(const u32*)&h01;
                    aP[mt][n2 * 2 + 1] = *(const u32*)&h23;
                }
            }

            #pragma unroll
            for (int vn = 0; vn < 4; vn++) {
                u32 b0, b1;
                ldmatrix_x2_trans(b0, b1,
                    Vs + (pt * 16 + (lane & 15)) * KV_STR + vn * 8);
                mma_f16(o[0][vn], aP[0], b0, b1);
                mma_f16(o[1][vn], aP[1], b0, b1);
            }
        }
    }

    #pragma unroll
    for (int mt = 0; mt < 2; mt++) {
        float s0 = rs0[mt];
        s0 += __shfl_xor_sync(0xffffffffu, s0, 1);
        s0 += __shfl_xor_sync(0xffffffffu, s0, 2);
        float s1 = rs1[mt];
        s1 += __shfl_xor_sync(0xffffffffu, s1, 1);
        s1 += __shfl_xor_sync(0xffffffffu, s1, 2);
        const float inv0 = 1.0f / s0;
        const float inv1 = 1.0f / s1;

        const int r0 = qt * 128 + w * 32 + mt * 16 + g;
        #pragma unroll
        for (int vn = 0; vn < 4; vn++) {
            const __half2 h0 = __floats2half2_rn(o[mt][vn][0] * inv0, o[mt][vn][1] * inv0);
            const __half2 h1 = __floats2half2_rn(o[mt][vn][2] * inv1, o[mt][vn][3] * inv1);
            *(u32*)(g_att16 + (l * 384 + r0)     * D + h * 32 + vn * 8 + 2 * tig) = *(const u32*)&h0;
            *(u32*)(g_att16 + (l * 384 + r0 + 8) * D + h * 32 + vn * 8 + 2 * tig) = *(const u32*)&h1;
        }
    }
}

// ---------------------------------------------------------------------------
// Kernel C: mean over n (fp16 in, fp32 math) + Wp + bp + skip.
// ---------------------------------------------------------------------------
__global__ __launch_bounds__(128)
void proj_kernel(const float* __restrict__ Wp,
                 const float* __restrict__ bp,
                 const float* __restrict__ skip,
                 float* __restrict__ out)
{
    __shared__ float ab[16][128];
    const int tid   = threadIdx.x;
    const int obase = blockIdx.x * 16;

    #pragma unroll
    for (int t = 0; t < 8; t++) {
        const int idx = tid + t * 128;
        const int r   = idx >> 6;
        const int cp  = idx & 63;
        const int o   = obase + r;
        const int L   = o >> 6;
        const int wi  = o & 63;
        float sx = 0.f, sy = 0.f;
        #pragma unroll
        for (int n = 0; n < 6; n++) {
            const u32 hv = *(const u32*)(g_att16 + (L * 384 + n * 64 + wi) * D + cp * 2);
            const float2 f = __half22float2(*(const __half2*)&hv);
            sx += f.x; sy += f.y;
        }
        ab[r][cp * 2]     = sx * (1.0f / 6.0f);
        ab[r][cp * 2 + 1] = sy * (1.0f / 6.0f);
    }
    __syncthreads();

    const int c = tid;
    float acc[16];
    const float bb = bp[c];
    #pragma unroll
    for (int r = 0; r < 16; r++) acc[r] = bb;

    #pragma unroll 4
    for (int j = 0; j < 128; j++) {
        const float w = Wp[j * 128 + c];
        #pragma unroll
        for (int r = 0; r < 16; r++) acc[r] = fmaf(ab[r][j], w, acc[r]);
    }
    #pragma unroll
    for (int r = 0; r < 16; r++) {
        const int o = obase + r;
        out[o * D + c] = acc[r] + skip[o * D + c];
    }
}

// ---------------------------------------------------------------------------
extern "C" void kernel_launch(void* const* d_in, const int* in_sizes, int n_in,
                              void* d_out, int out_size)
{
    const float* q          = (const float*)d_in[0];
    const float* k          = (const float*)d_in[1];
    const float* v          = (const float*)d_in[2];
    const float* skip       = (const float*)d_in[3];
    const float* attn_scale = (const float*)d_in[4];
    const float* lnq_g = (const float*)d_in[5];
    const float* lnq_b = (const float*)d_in[6];
    const float* Wq    = (const float*)d_in[7];
    const float* bq    = (const float*)d_in[8];
    const float* lnk_g = (const float*)d_in[9];
    const float* lnk_b = (const float*)d_in[10];
    const float* Wk    = (const float*)d_in[11];
    const float* bk    = (const float*)d_in[12];
    const float* lnv_g = (const float*)d_in[13];
    const float* lnv_b = (const float*)d_in[14];
    const float* Wv    = (const float*)d_in[15];
    const float* bv    = (const float*)d_in[16];
    const float* Wp    = (const float*)d_in[17];
    const float* bp    = (const float*)d_in[18];
    float* out = (float*)d_out;

    static int smem_set = 0;
    if (!smem_set) {
        cudaFuncSetAttribute(ln_all_kernel,
                             cudaFuncAttributeMaxDynamicSharedMemorySize,
                             LN_SMEM_BYTES);
        smem_set = 1;
    }

    ln_all_kernel<<<1344, 128, LN_SMEM_BYTES>>>(q, k, v, attn_scale,
                                                lnq_g, lnq_b, Wq, bq,
                                                lnk_g, lnk_b, Wk, bk,
                                                lnv_g, lnv_b, Wv, bv);

    attn_kernel<<<768, 128>>>(attn_scale);

    proj_kernel<<<4096 / 16, 128>>>(Wp, bp, skip, out);
}

// round 16
// speedup vs baseline: 1.2553x; 1.2553x over previous
#include <cuda_runtime.h>
#include <cuda_fp16.h>

// ---------------------------------------------------------------------------
// CrossViewSwapAttention — tf32-MMA LN-GEMM -> fp16 q/k/v -> fp16-MMA flash
// attention (coef pre-folded into Q) -> fp16 att -> proj (8 rows/block).
//   qf (L=64, Nq=384, d=128), kf/vf (L=64, Nk=480, d=128), heads 4 x dh 32.
// ---------------------------------------------------------------------------

#define NQ_ROWS  24576
#define NK_ROWS  30720
#define D        128

__device__ __half g_q16 [NQ_ROWS * D];
__device__ __half g_k16 [NK_ROWS * D];
__device__ __half g_v16 [NK_ROWS * D];
__device__ __half g_att16[NQ_ROWS * D];

typedef unsigned long long u64;
typedef unsigned int u32;

__device__ __forceinline__ float ex2(float x) {
    float r;
    asm("ex2.approx.f32 %0, %1;" : "=f"(r) : "f"(x));
    return r;
}
__device__ __forceinline__ u32 cvt_tf32(float x) {
    u32 r;
    asm("cvt.rna.tf32.f32 %0, %1;" : "=r"(r) : "f"(x));
    return r;
}
__device__ __forceinline__ void mma_tf32(float c[4], const u32 a[4], u32 b0, u32 b1) {
    asm("mma.sync.aligned.m16n8k8.row.col.f32.tf32.tf32.f32 "
        "{%0,%1,%2,%3}, {%4,%5,%6,%7}, {%8,%9}, {%0,%1,%2,%3};"
        : "+f"(c[0]), "+f"(c[1]), "+f"(c[2]), "+f"(c[3])
        : "r"(a[0]), "r"(a[1]), "r"(a[2]), "r"(a[3]), "r"(b0), "r"(b1));
}
__device__ __forceinline__ void mma_f16(float c[4], const u32 a[4], u32 b0, u32 b1) {
    asm("mma.sync.aligned.m16n8k16.row.col.f32.f16.f16.f32 "
        "{%0,%1,%2,%3}, {%4,%5,%6,%7}, {%8,%9}, {%0,%1,%2,%3};"
        : "+f"(c[0]), "+f"(c[1]), "+f"(c[2]), "+f"(c[3])
        : "r"(a[0]), "r"(a[1]), "r"(a[2]), "r"(a[3]), "r"(b0), "r"(b1));
}
__device__ __forceinline__ void ldmatrix_x2_trans(u32& r0, u32& r1, const void* p) {
    u32 addr = (u32)__cvta_generic_to_shared(p);
    asm volatile("ldmatrix.sync.aligned.m8n8.x2.trans.shared.b16 {%0,%1}, [%2];"
                 : "=r"(r0), "=r"(r1) : "r"(addr));
}

// ---------------------------------------------------------------------------
// Kernel A: fused LayerNorm + tf32-MMA Linear (R14 measured-best, verbatim).
// Q outputs pre-scaled by attn_scale * dh^-0.5 * log2e (linear fold).
// ---------------------------------------------------------------------------
#define XS_STRIDE 132
#define WS_STRIDE 136
#define LN_SMEM_BYTES (64 * XS_STRIDE * 4 + 32 * WS_STRIDE * 4)   // 51200 B

__global__ __launch_bounds__(128, 4)
void ln_all_kernel(const float* __restrict__ q,
                   const float* __restrict__ k,
                   const float* __restrict__ v,
                   const float* __restrict__ scale_ptr,
                   const float* __restrict__ lnq_g, const float* __restrict__ lnq_b,
                   const float* __restrict__ Wq,    const float* __restrict__ bq,
                   const float* __restrict__ lnk_g, const float* __restrict__ lnk_b,
                   const float* __restrict__ Wk,    const float* __restrict__ bk,
                   const float* __restrict__ lnv_g, const float* __restrict__ lnv_b,
                   const float* __restrict__ Wv,    const float* __restrict__ bv)
{
    extern __shared__ float smem[];
    float* Xs  = smem;                      // [64][132]
    float* W_s = smem + 64 * XS_STRIDE;     // [32][136]

    const int bx   = blockIdx.x;
    const int tid  = threadIdx.x;
    const int warp = tid >> 5;
    const int lane = tid & 31;

    const float *x, *gamma, *beta, *W, *blin;
    __half* out16;
    int rowsPerL, perN, rbase;
    float cf = 1.0f;
    if (bx < 384) {
        x = q; gamma = lnq_g; beta = lnq_b; W = Wq; blin = bq;
        out16 = g_q16; rowsPerL = 384; perN = 64; rbase = bx * 64;
        cf = scale_ptr[0] * 0.17677669529663687f * 1.4426950408889634f;
    } else if (bx < 864) {
        x = k; gamma = lnk_g; beta = lnk_b; W = Wk; blin = bk;
        out16 = g_k16; rowsPerL = 480; perN = 80; rbase = (bx - 384) * 64;
    } else {
        x = v; gamma = lnv_g; beta = lnv_b; W = Wv; blin = bv;
        out16 = g_v16; rowsPerL = 480; perN = 80; rbase = (bx - 864) * 64;
    }

    const float g0 = gamma[lane],      g1 = gamma[lane + 32],
                g2 = gamma[lane + 64], g3 = gamma[lane + 96];
    const float b0 = beta[lane],       b1 = beta[lane + 32],
                b2 = beta[lane + 64],  b3 = beta[lane + 96];

    #pragma unroll 4
    for (int rr = 0; rr < 16; rr++) {
        const int r   = warp * 16 + rr;
        const int row = rbase + r;
        const int L   = row / rowsPerL;
        const int N   = row - L * rowsPerL;
        const int nn  = N / perN;
        const int wi  = N - nn * perN;
        const float* xr = x + ((nn * 64 + L) * perN + wi) * D;

        const float v0 = xr[lane],      v1 = xr[lane + 32],
                    v2 = xr[lane + 64], v3 = xr[lane + 96];
        float s = v0 + v1 + v2 + v3;
        #pragma unroll
        for (int o = 16; o; o >>= 1) s += __shfl_xor_sync(0xffffffffu, s, o);
        const float mu = s * (1.0f / 128.0f);
        const float d0 = v0 - mu, d1 = v1 - mu, d2 = v2 - mu, d3 = v3 - mu;
        float sq = d0 * d0 + d1 * d1 + d2 * d2 + d3 * d3;
        #pragma unroll
        for (int o = 16; o; o >>= 1) sq += __shfl_xor_sync(0xffffffffu, sq, o);
        const float rstd = rsqrtf(sq * (1.0f / 128.0f) + 1e-5f);

        float* xd = Xs + r * XS_STRIDE;
        xd[lane]      = __uint_as_float(cvt_tf32(d0 * rstd * g0 + b0));
        xd[lane + 32] = __uint_as_float(cvt_tf32(d1 * rstd * g1 + b1));
        xd[lane + 64] = __uint_as_float(cvt_tf32(d2 * rstd * g2 + b2));
        xd[lane + 96] = __uint_as_float(cvt_tf32(d3 * rstd * g3 + b3));
    }

    const int g   = lane >> 2;
    const int tig = lane & 3;
    const int mh  = warp >> 1;
    const int nh  = warp & 1;

    float acc[2][8][4];
    #pragma unroll
    for (int mt = 0; mt < 2; mt++)
        #pragma unroll
        for (int nt = 0; nt < 8; nt++)
            #pragma unroll
            for (int i = 0; i < 4; i++) acc[mt][nt][i] = 0.0f;

    for (int q4 = 0; q4 < 4; q4++) {
        __syncthreads();
        #pragma unroll
        for (int t = 0; t < 8; t++) {
            const int idx = tid + t * 128;
            const int j   = idx >> 5;
            const int c4  = idx & 31;
            const float4 f = *(const float4*)(W + (q4 * 32 + j) * 128 + c4 * 4);
            float* d = W_s + j * WS_STRIDE + c4 * 4;
            d[0] = __uint_as_float(cvt_tf32(f.x));
            d[1] = __uint_as_float(cvt_tf32(f.y));
            d[2] = __uint_as_float(cvt_tf32(f.z));
            d[3] = __uint_as_float(cvt_tf32(f.w));
        }
        __syncthreads();

        #pragma unroll
        for (int ks = 0; ks < 4; ks++) {
            const int kk = q4 * 32 + ks * 8;
            u32 a[2][4];
            #pragma unroll
            for (int mt = 0; mt < 2; mt++) {
                const int r0 = mh * 32 + mt * 16;
                a[mt][0] = __float_as_uint(Xs[(r0 + g)     * XS_STRIDE + kk + tig]);
                a[mt][1] = __float_as_uint(Xs[(r0 + g + 8) * XS_STRIDE + kk + tig]);
                a[mt][2] = __float_as_uint(Xs[(r0 + g)     * XS_STRIDE + kk + tig + 4]);
                a[mt][3] = __float_as_uint(Xs[(r0 + g + 8) * XS_STRIDE + kk + tig + 4]);
            }
            #pragma unroll
            for (int nt = 0; nt < 8; nt++) {
                const int n0 = nh * 64 + nt * 8;
                const u32 bb0 = __float_as_uint(W_s[(ks * 8 + tig)     * WS_STRIDE + n0 + g]);
                const u32 bb1 = __float_as_uint(W_s[(ks * 8 + tig + 4) * WS_STRIDE + n0 + g]);
                mma_tf32(acc[0][nt], a[0], bb0, bb1);
                mma_tf32(acc[1][nt], a[1], bb0, bb1);
            }
        }
    }

    #pragma unroll
    for (int mt = 0; mt < 2; mt++) {
        const int r0 = rbase + mh * 32 + mt * 16;
        #pragma unroll
        for (int nt = 0; nt < 8; nt++) {
            const int col = nh * 64 + nt * 8 + 2 * tig;
            const float2 bb = *(const float2*)(blin + col);
            const __half2 h0 = __floats2half2_rn((acc[mt][nt][0] + bb.x) * cf,
                                                 (acc[mt][nt][1] + bb.y) * cf);
            const __half2 h1 = __floats2half2_rn((acc[mt][nt][2] + bb.x) * cf,
                                                 (acc[mt][nt][3] + bb.y) * cf);
            *(u32*)(out16 + (r0 + g)     * D + col) = *(const u32*)&h0;
            *(u32*)(out16 + (r0 + g + 8) * D + col) = *(const u32*)&h1;
        }
    }
}

// ---------------------------------------------------------------------------
// Kernel B: fp16 tensor-core flash attention (R14 measured-best, verbatim).
// ---------------------------------------------------------------------------
#define KV_STR 40

__global__ __launch_bounds__(128, 5)
void attn_kernel(const float* __restrict__ scale_ptr)
{
    __shared__ __half Ks[96 * KV_STR];
    __shared__ __half Vs[96 * KV_STR];

    const int bx   = blockIdx.x;
    const int h    = bx & 3;
    const int l    = (bx >> 2) & 63;
    const int qt   = bx >> 8;
    const int tid  = threadIdx.x;
    const int w    = tid >> 5;
    const int lane = tid & 31;
    const int g    = lane >> 2;
    const int tig  = lane & 3;

    const __half* qbase = g_q16 + (l * 384 + qt * 128) * D + h * 32;
    const __half* kbase = g_k16 + (l * 480) * D + h * 32;
    const __half* vbase = g_v16 + (l * 480) * D + h * 32;

    u32 qa[2][2][4];
    #pragma unroll
    for (int mt = 0; mt < 2; mt++) {
        #pragma unroll
        for (int ks = 0; ks < 2; ks++) {
            const __half* p = qbase + (w * 32 + mt * 16 + g) * D + ks * 16 + 2 * tig;
            qa[mt][ks][0] = *(const u32*)(p);
            qa[mt][ks][1] = *(const u32*)(p + 8 * D);
            qa[mt][ks][2] = *(const u32*)(p + 8);
            qa[mt][ks][3] = *(const u32*)(p + 8 * D + 8);
        }
    }

    float o[2][4][4];
    #pragma unroll
    for (int mt = 0; mt < 2; mt++)
        #pragma unroll
        for (int vn = 0; vn < 4; vn++)
            #pragma unroll
            for (int i = 0; i < 4; i++) o[mt][vn][i] = 0.0f;
    float rs0[2] = {0.f, 0.f};
    float rs1[2] = {0.f, 0.f};

    for (int c0 = 0; c0 < 480; c0 += 96) {
        __syncthreads();
        #pragma unroll
        for (int t = 0; t < 3; t++) {
            const int idx = tid + t * 128;
            const int row = idx >> 2;
            const int seg = idx & 3;
            *(float4*)(Ks + row * KV_STR + seg * 8) =
                *(const float4*)(kbase + (c0 + row) * D + seg * 8);
            *(float4*)(Vs + row * KV_STR + seg * 8) =
                *(const float4*)(vbase + (c0 + row) * D + seg * 8);
        }
        __syncthreads();

        #pragma unroll
        for (int pt = 0; pt < 6; pt++) {
            float s[2][2][4];
            #pragma unroll
            for (int mt = 0; mt < 2; mt++)
                #pragma unroll
                for (int n2 = 0; n2 < 2; n2++)
                    #pragma unroll
                    for (int i = 0; i < 4; i++) s[mt][n2][i] = 0.0f;

            #pragma unroll
            for (int n2 = 0; n2 < 2; n2++) {
                const int n0 = pt * 16 + n2 * 8;
                #pragma unroll
                for (int ks = 0; ks < 2; ks++) {
                    const __half* kp = Ks + (n0 + g) * KV_STR + ks * 16 + 2 * tig;
                    const u32 b0 = *(const u32*)(kp);
                    const u32 b1 = *(const u32*)(kp + 8);
                    mma_f16(s[0][n2], qa[0][ks], b0, b1);
                    mma_f16(s[1][n2], qa[1][ks], b0, b1);
                }
            }

            u32 aP[2][4];
            #pragma unroll
            for (int mt = 0; mt < 2; mt++) {
                #pragma unroll
                for (int n2 = 0; n2 < 2; n2++) {
                    const float p0 = ex2(s[mt][n2][0]);
                    const float p1 = ex2(s[mt][n2][1]);
                    const float p2 = ex2(s[mt][n2][2]);
                    const float p3 = ex2(s[mt][n2][3]);
                    rs0[mt] += p0 + p1;
                    rs1[mt] += p2 + p3;
                    const __half2 h01 = __floats2half2_rn(p0, p1);
                    const __half2 h23 = __floats2half2_rn(p2, p3);
                    aP[mt][n2 * 2 + 0] = *(const u32*)&h01;
                    aP[mt][n2 * 2 + 1] = *(const u32*)&h23;
                }
            }

            #pragma unroll
            for (int vn = 0; vn < 4; vn++) {
                u32 b0, b1;
                ldmatrix_x2_trans(b0, b1,
                    Vs + (pt * 16 + (lane & 15)) * KV_STR + vn * 8);
                mma_f16(o[0][vn], aP[0], b0, b1);
                mma_f16(o[1][vn], aP[1], b0, b1);
            }
        }
    }

    #pragma unroll
    for (int mt = 0; mt < 2; mt++) {
        float s0 = rs0[mt];
        s0 += __shfl_xor_sync(0xffffffffu, s0, 1);
        s0 += __shfl_xor_sync(0xffffffffu, s0, 2);
        float s1 = rs1[mt];
        s1 += __shfl_xor_sync(0xffffffffu, s1, 1);
        s1 += __shfl_xor_sync(0xffffffffu, s1, 2);
        const float inv0 = 1.0f / s0;
        const float inv1 = 1.0f / s1;

        const int r0 = qt * 128 + w * 32 + mt * 16 + g;
        #pragma unroll
        for (int vn = 0; vn < 4; vn++) {
            const __half2 h0 = __floats2half2_rn(o[mt][vn][0] * inv0, o[mt][vn][1] * inv0);
            const __half2 h1 = __floats2half2_rn(o[mt][vn][2] * inv1, o[mt][vn][3] * inv1);
            *(u32*)(g_att16 + (l * 384 + r0)     * D + h * 32 + vn * 8 + 2 * tig) = *(const u32*)&h0;
            *(u32*)(g_att16 + (l * 384 + r0 + 8) * D + h * 32 + vn * 8 + 2 * tig) = *(const u32*)&h1;
        }
    }
}

// ---------------------------------------------------------------------------
// Kernel C: mean over n (fp16 in, fp32 math) + Wp + bp + skip.
// 8 rows/block -> 512 blocks (~3.5 blocks/SM) for latency hiding.
// ---------------------------------------------------------------------------
__global__ __launch_bounds__(128)
void proj_kernel(const float* __restrict__ Wp,
                 const float* __restrict__ bp,
                 const float* __restrict__ skip,
                 float* __restrict__ out)
{
    __shared__ float ab[8][128];
    const int tid   = threadIdx.x;
    const int obase = blockIdx.x * 8;

    // 6-view mean: 8 rows x 64 column-pairs = 512 entries, half2 loads.
    #pragma unroll
    for (int t = 0; t < 4; t++) {
        const int idx = tid + t * 128;
        const int r   = idx >> 6;
        const int cp  = idx & 63;
        const int o   = obase + r;
        const int L   = o >> 6;
        const int wi  = o & 63;
        float sx = 0.f, sy = 0.f;
        #pragma unroll
        for (int n = 0; n < 6; n++) {
            const u32 hv = *(const u32*)(g_att16 + (L * 384 + n * 64 + wi) * D + cp * 2);
            const float2 f = __half22float2(*(const __half2*)&hv);
            sx += f.x; sy += f.y;
        }
        ab[r][cp * 2]     = sx * (1.0f / 6.0f);
        ab[r][cp * 2 + 1] = sy * (1.0f / 6.0f);
    }
    __syncthreads();

    const int c = tid;
    float acc[8];
    const float bb = bp[c];
    #pragma unroll
    for (int r = 0; r < 8; r++) acc[r] = bb;

    #pragma unroll 8
    for (int j = 0; j < 128; j++) {
        const float w = Wp[j * 128 + c];
        #pragma unroll
        for (int r = 0; r < 8; r++) acc[r] = fmaf(ab[r][j], w, acc[r]);
    }
    #pragma unroll
    for (int r = 0; r < 8; r++) {
        const int o = obase + r;
        out[o * D + c] = acc[r] + skip[o * D + c];
    }
}

// ---------------------------------------------------------------------------
extern "C" void kernel_launch(void* const* d_in, const int* in_sizes, int n_in,
                              void* d_out, int out_size)
{
    const float* q          = (const float*)d_in[0];
    const float* k          = (const float*)d_in[1];
    const float* v          = (const float*)d_in[2];
    const float* skip       = (const float*)d_in[3];
    const float* attn_scale = (const float*)d_in[4];
    const float* lnq_g = (const float*)d_in[5];
    const float* lnq_b = (const float*)d_in[6];
    const float* Wq    = (const float*)d_in[7];
    const float* bq    = (const float*)d_in[8];
    const float* lnk_g = (const float*)d_in[9];
    const float* lnk_b = (const float*)d_in[10];
    const float* Wk    = (const float*)d_in[11];
    const float* bk    = (const float*)d_in[12];
    const float* lnv_g = (const float*)d_in[13];
    const float* lnv_b = (const float*)d_in[14];
    const float* Wv    = (const float*)d_in[15];
    const float* bv    = (const float*)d_in[16];
    const float* Wp    = (const float*)d_in[17];
    const float* bp    = (const float*)d_in[18];
    float* out = (float*)d_out;

    static int smem_set = 0;
    if (!smem_set) {
        cudaFuncSetAttribute(ln_all_kernel,
                             cudaFuncAttributeMaxDynamicSharedMemorySize,
                             LN_SMEM_BYTES);
        smem_set = 1;
    }

    ln_all_kernel<<<1344, 128, LN_SMEM_BYTES>>>(q, k, v, attn_scale,
                                                lnq_g, lnq_b, Wq, bq,
                                                lnk_g, lnk_b, Wk, bk,
                                                lnv_g, lnv_b, Wv, bv);

    attn_kernel<<<768, 128>>>(attn_scale);

    proj_kernel<<<4096 / 8, 128>>>(Wp, bp, skip, out);
}

// round 17
// speedup vs baseline: 1.2666x; 1.0091x over previous
#include <cuda_runtime.h>
#include <cuda_fp16.h>

// ---------------------------------------------------------------------------
// CrossViewSwapAttention — tf32-MMA LN-GEMM (fused-moment reduction, 5 blk/SM)
// -> fp16 q/k/v -> fp16-MMA flash attention (coef pre-folded into Q)
// -> fp16 att -> proj (8 rows/block).
//   qf (L=64, Nq=384, d=128), kf/vf (L=64, Nk=480, d=128), heads 4 x dh 32.
// ---------------------------------------------------------------------------

#define NQ_ROWS  24576
#define NK_ROWS  30720
#define D        128

__device__ __half g_q16 [NQ_ROWS * D];
__device__ __half g_k16 [NK_ROWS * D];
__device__ __half g_v16 [NK_ROWS * D];
__device__ __half g_att16[NQ_ROWS * D];

typedef unsigned long long u64;
typedef unsigned int u32;

__device__ __forceinline__ float ex2(float x) {
    float r;
    asm("ex2.approx.f32 %0, %1;" : "=f"(r) : "f"(x));
    return r;
}
__device__ __forceinline__ u32 cvt_tf32(float x) {
    u32 r;
    asm("cvt.rna.tf32.f32 %0, %1;" : "=r"(r) : "f"(x));
    return r;
}
__device__ __forceinline__ void mma_tf32(float c[4], const u32 a[4], u32 b0, u32 b1) {
    asm("mma.sync.aligned.m16n8k8.row.col.f32.tf32.tf32.f32 "
        "{%0,%1,%2,%3}, {%4,%5,%6,%7}, {%8,%9}, {%0,%1,%2,%3};"
        : "+f"(c[0]), "+f"(c[1]), "+f"(c[2]), "+f"(c[3])
        : "r"(a[0]), "r"(a[1]), "r"(a[2]), "r"(a[3]), "r"(b0), "r"(b1));
}
__device__ __forceinline__ void mma_f16(float c[4], const u32 a[4], u32 b0, u32 b1) {
    asm("mma.sync.aligned.m16n8k16.row.col.f32.f16.f16.f32 "
        "{%0,%1,%2,%3}, {%4,%5,%6,%7}, {%8,%9}, {%0,%1,%2,%3};"
        : "+f"(c[0]), "+f"(c[1]), "+f"(c[2]), "+f"(c[3])
        : "r"(a[0]), "r"(a[1]), "r"(a[2]), "r"(a[3]), "r"(b0), "r"(b1));
}
__device__ __forceinline__ void ldmatrix_x2_trans(u32& r0, u32& r1, const void* p) {
    u32 addr = (u32)__cvta_generic_to_shared(p);
    asm volatile("ldmatrix.sync.aligned.m8n8.x2.trans.shared.b16 {%0,%1}, [%2];"
                 : "=r"(r0), "=r"(r1) : "r"(addr));
}

// ---------------------------------------------------------------------------
// Kernel A: fused LayerNorm + tf32-MMA Linear.
// Phase 1: single fused moment reduction (s, sq together; Var = E[x^2]-mu^2).
// Phase 2: 16-row W quarter-buffer (8 refills) -> smem 42496 B, 5 blocks/SM.
// Q outputs pre-scaled by attn_scale * dh^-0.5 * log2e (linear fold).
// ---------------------------------------------------------------------------
#define XS_STRIDE 132
#define WS_STRIDE 136
#define LN_SMEM_BYTES (64 * XS_STRIDE * 4 + 16 * WS_STRIDE * 4)   // 42496 B

__global__ __launch_bounds__(128, 5)
void ln_all_kernel(const float* __restrict__ q,
                   const float* __restrict__ k,
                   const float* __restrict__ v,
                   const float* __restrict__ scale_ptr,
                   const float* __restrict__ lnq_g, const float* __restrict__ lnq_b,
                   const float* __restrict__ Wq,    const float* __restrict__ bq,
                   const float* __restrict__ lnk_g, const float* __restrict__ lnk_b,
                   const float* __restrict__ Wk,    const float* __restrict__ bk,
                   const float* __restrict__ lnv_g, const float* __restrict__ lnv_b,
                   const float* __restrict__ Wv,    const float* __restrict__ bv)
{
    extern __shared__ float smem[];
    float* Xs  = smem;                      // [64][132]
    float* W_s = smem + 64 * XS_STRIDE;     // [16][136]

    const int bx   = blockIdx.x;
    const int tid  = threadIdx.x;
    const int warp = tid >> 5;
    const int lane = tid & 31;

    const float *x, *gamma, *beta, *W, *blin;
    __half* out16;
    int rowsPerL, perN, rbase;
    float cf = 1.0f;
    if (bx < 384) {
        x = q; gamma = lnq_g; beta = lnq_b; W = Wq; blin = bq;
        out16 = g_q16; rowsPerL = 384; perN = 64; rbase = bx * 64;
        cf = scale_ptr[0] * 0.17677669529663687f * 1.4426950408889634f;
    } else if (bx < 864) {
        x = k; gamma = lnk_g; beta = lnk_b; W = Wk; blin = bk;
        out16 = g_k16; rowsPerL = 480; perN = 80; rbase = (bx - 384) * 64;
    } else {
        x = v; gamma = lnv_g; beta = lnv_b; W = Wv; blin = bv;
        out16 = g_v16; rowsPerL = 480; perN = 80; rbase = (bx - 864) * 64;
    }

    const float g0 = gamma[lane],      g1 = gamma[lane + 32],
                g2 = gamma[lane + 64], g3 = gamma[lane + 96];
    const float b0 = beta[lane],       b1 = beta[lane + 32],
                b2 = beta[lane + 64],  b3 = beta[lane + 96];

    // Phase 1: fused-moment LN. Both reductions share one 5-step shfl loop.
    #pragma unroll 4
    for (int rr = 0; rr < 16; rr++) {
        const int r   = warp * 16 + rr;
        const int row = rbase + r;
        const int L   = row / rowsPerL;
        const int N   = row - L * rowsPerL;
        const int nn  = N / perN;
        const int wi  = N - nn * perN;
        const float* xr = x + ((nn * 64 + L) * perN + wi) * D;

        const float v0 = xr[lane],      v1 = xr[lane + 32],
                    v2 = xr[lane + 64], v3 = xr[lane + 96];
        float s  = v0 + v1 + v2 + v3;
        float sq = v0 * v0 + v1 * v1 + v2 * v2 + v3 * v3;
        #pragma unroll
        for (int o = 16; o; o >>= 1) {
            s  += __shfl_xor_sync(0xffffffffu, s, o);
            sq += __shfl_xor_sync(0xffffffffu, sq, o);
        }
        const float mu  = s * (1.0f / 128.0f);
        const float var = sq * (1.0f / 128.0f) - mu * mu;
        const float rstd = rsqrtf(var + 1e-5f);

        float* xd = Xs + r * XS_STRIDE;
        xd[lane]      = __uint_as_float(cvt_tf32((v0 - mu) * rstd * g0 + b0));
        xd[lane + 32] = __uint_as_float(cvt_tf32((v1 - mu) * rstd * g1 + b1));
        xd[lane + 64] = __uint_as_float(cvt_tf32((v2 - mu) * rstd * g2 + b2));
        xd[lane + 96] = __uint_as_float(cvt_tf32((v3 - mu) * rstd * g3 + b3));
    }

    // Phase 2: tf32 MMA, 16-row W quarters (8 refills).
    const int g   = lane >> 2;
    const int tig = lane & 3;
    const int mh  = warp >> 1;
    const int nh  = warp & 1;

    float acc[2][8][4];
    #pragma unroll
    for (int mt = 0; mt < 2; mt++)
        #pragma unroll
        for (int nt = 0; nt < 8; nt++)
            #pragma unroll
            for (int i = 0; i < 4; i++) acc[mt][nt][i] = 0.0f;

    for (int q8 = 0; q8 < 8; q8++) {
        __syncthreads();   // phase-1 done (first iter) / previous quarter consumed
        // Stage W rows [q8*16, q8*16+16): 2048 floats = 4 float4 per thread.
        #pragma unroll
        for (int t = 0; t < 4; t++) {
            const int idx = tid + t * 128;
            const int j   = idx >> 5;        // 0..15
            const int c4  = idx & 31;
            const float4 f = *(const float4*)(W + (q8 * 16 + j) * 128 + c4 * 4);
            float* d = W_s + j * WS_STRIDE + c4 * 4;
            d[0] = __uint_as_float(cvt_tf32(f.x));
            d[1] = __uint_as_float(cvt_tf32(f.y));
            d[2] = __uint_as_float(cvt_tf32(f.z));
            d[3] = __uint_as_float(cvt_tf32(f.w));
        }
        __syncthreads();

        #pragma unroll
        for (int ks = 0; ks < 2; ks++) {
            const int kk = q8 * 16 + ks * 8;
            u32 a[2][4];
            #pragma unroll
            for (int mt = 0; mt < 2; mt++) {
                const int r0 = mh * 32 + mt * 16;
                a[mt][0] = __float_as_uint(Xs[(r0 + g)     * XS_STRIDE + kk + tig]);
                a[mt][1] = __float_as_uint(Xs[(r0 + g + 8) * XS_STRIDE + kk + tig]);
                a[mt][2] = __float_as_uint(Xs[(r0 + g)     * XS_STRIDE + kk + tig + 4]);
                a[mt][3] = __float_as_uint(Xs[(r0 + g + 8) * XS_STRIDE + kk + tig + 4]);
            }
            #pragma unroll
            for (int nt = 0; nt < 8; nt++) {
                const int n0 = nh * 64 + nt * 8;
                const u32 bb0 = __float_as_uint(W_s[(ks * 8 + tig)     * WS_STRIDE + n0 + g]);
                const u32 bb1 = __float_as_uint(W_s[(ks * 8 + tig + 4) * WS_STRIDE + n0 + g]);
                mma_tf32(acc[0][nt], a[0], bb0, bb1);
                mma_tf32(acc[1][nt], a[1], bb0, bb1);
            }
        }
    }

    // Epilogue: + bias, (Q only) * coef, pack fp16.
    #pragma unroll
    for (int mt = 0; mt < 2; mt++) {
        const int r0 = rbase + mh * 32 + mt * 16;
        #pragma unroll
        for (int nt = 0; nt < 8; nt++) {
            const int col = nh * 64 + nt * 8 + 2 * tig;
            const float2 bb = *(const float2*)(blin + col);
            const __half2 h0 = __floats2half2_rn((acc[mt][nt][0] + bb.x) * cf,
                                                 (acc[mt][nt][1] + bb.y) * cf);
            const __half2 h1 = __floats2half2_rn((acc[mt][nt][2] + bb.x) * cf,
                                                 (acc[mt][nt][3] + bb.y) * cf);
            *(u32*)(out16 + (r0 + g)     * D + col) = *(const u32*)&h0;
            *(u32*)(out16 + (r0 + g + 8) * D + col) = *(const u32*)&h1;
        }
    }
}

// ---------------------------------------------------------------------------
// Kernel B: fp16 tensor-core flash attention (R14 measured-best, verbatim).
// ---------------------------------------------------------------------------
#define KV_STR 40

__global__ __launch_bounds__(128, 5)
void attn_kernel(const float* __restrict__ scale_ptr)
{
    __shared__ __half Ks[96 * KV_STR];
    __shared__ __half Vs[96 * KV_STR];

    const int bx   = blockIdx.x;
    const int h    = bx & 3;
    const int l    = (bx >> 2) & 63;
    const int qt   = bx >> 8;
    const int tid  = threadIdx.x;
    const int w    = tid >> 5;
    const int lane = tid & 31;
    const int g    = lane >> 2;
    const int tig  = lane & 3;

    const __half* qbase = g_q16 + (l * 384 + qt * 128) * D + h * 32;
    const __half* kbase = g_k16 + (l * 480) * D + h * 32;
    const __half* vbase = g_v16 + (l * 480) * D + h * 32;

    u32 qa[2][2][4];
    #pragma unroll
    for (int mt = 0; mt < 2; mt++) {
        #pragma unroll
        for (int ks = 0; ks < 2; ks++) {
            const __half* p = qbase + (w * 32 + mt * 16 + g) * D + ks * 16 + 2 * tig;
            qa[mt][ks][0] = *(const u32*)(p);
            qa[mt][ks][1] = *(const u32*)(p + 8 * D);
            qa[mt][ks][2] = *(const u32*)(p + 8);
            qa[mt][ks][3] = *(const u32*)(p + 8 * D + 8);
        }
    }

    float o[2][4][4];
    #pragma unroll
    for (int mt = 0; mt < 2; mt++)
        #pragma unroll
        for (int vn = 0; vn < 4; vn++)
            #pragma unroll
            for (int i = 0; i < 4; i++) o[mt][vn][i] = 0.0f;
    float rs0[2] = {0.f, 0.f};
    float rs1[2] = {0.f, 0.f};

    for (int c0 = 0; c0 < 480; c0 += 96) {
        __syncthreads();
        #pragma unroll
        for (int t = 0; t < 3; t++) {
            const int idx = tid + t * 128;
            const int row = idx >> 2;
            const int seg = idx & 3;
            *(float4*)(Ks + row * KV_STR + seg * 8) =
                *(const float4*)(kbase + (c0 + row) * D + seg * 8);
            *(float4*)(Vs + row * KV_STR + seg * 8) =
                *(const float4*)(vbase + (c0 + row) * D + seg * 8);
        }
        __syncthreads();

        #pragma unroll
        for (int pt = 0; pt < 6; pt++) {
            float s[2][2][4];
            #pragma unroll
            for (int mt = 0; mt < 2; mt++)
                #pragma unroll
                for (int n2 = 0; n2 < 2; n2++)
                    #pragma unroll
                    for (int i = 0; i < 4; i++) s[mt][n2][i] = 0.0f;

            #pragma unroll
            for (int n2 = 0; n2 < 2; n2++) {
                const int n0 = pt * 16 + n2 * 8;
                #pragma unroll
                for (int ks = 0; ks < 2; ks++) {
                    const __half* kp = Ks + (n0 + g) * KV_STR + ks * 16 + 2 * tig;
                    const u32 b0 = *(const u32*)(kp);
                    const u32 b1 = *(const u32*)(kp + 8);
                    mma_f16(s[0][n2], qa[0][ks], b0, b1);
                    mma_f16(s[1][n2], qa[1][ks], b0, b1);
                }
            }

            u32 aP[2][4];
            #pragma unroll
            for (int mt = 0; mt < 2; mt++) {
                #pragma unroll
                for (int n2 = 0; n2 < 2; n2++) {
                    const float p0 = ex2(s[mt][n2][0]);
                    const float p1 = ex2(s[mt][n2][1]);
                    const float p2 = ex2(s[mt][n2][2]);
                    const float p3 = ex2(s[mt][n2][3]);
                    rs0[mt] += p0 + p1;
                    rs1[mt] += p2 + p3;
                    const __half2 h01 = __floats2half2_rn(p0, p1);
                    const __half2 h23 = __floats2half2_rn(p2, p3);
                    aP[mt][n2 * 2 + 0] = *(const u32*)&h01;
                    aP[mt][n2 * 2 + 1] = *(const u32*)&h23;
                }
            }

            #pragma unroll
            for (int vn = 0; vn < 4; vn++) {
                u32 b0, b1;
                ldmatrix_x2_trans(b0, b1,
                    Vs + (pt * 16 + (lane & 15)) * KV_STR + vn * 8);
                mma_f16(o[0][vn], aP[0], b0, b1);
                mma_f16(o[1][vn], aP[1], b0, b1);
            }
        }
    }

    #pragma unroll
    for (int mt = 0; mt < 2; mt++) {
        float s0 = rs0[mt];
        s0 += __shfl_xor_sync(0xffffffffu, s0, 1);
        s0 += __shfl_xor_sync(0xffffffffu, s0, 2);
        float s1 = rs1[mt];
        s1 += __shfl_xor_sync(0xffffffffu, s1, 1);
        s1 += __shfl_xor_sync(0xffffffffu, s1, 2);
        const float inv0 = 1.0f / s0;
        const float inv1 = 1.0f / s1;

        const int r0 = qt * 128 + w * 32 + mt * 16 + g;
        #pragma unroll
        for (int vn = 0; vn < 4; vn++) {
            const __half2 h0 = __floats2half2_rn(o[mt][vn][0] * inv0, o[mt][vn][1] * inv0);
            const __half2 h1 = __floats2half2_rn(o[mt][vn][2] * inv1, o[mt][vn][3] * inv1);
            *(u32*)(g_att16 + (l * 384 + r0)     * D + h * 32 + vn * 8 + 2 * tig) = *(const u32*)&h0;
            *(u32*)(g_att16 + (l * 384 + r0 + 8) * D + h * 32 + vn * 8 + 2 * tig) = *(const u32*)&h1;
        }
    }
}

// ---------------------------------------------------------------------------
// Kernel C: mean over n (fp16 in, fp32 math) + Wp + bp + skip. 8 rows/block.
// ---------------------------------------------------------------------------
__global__ __launch_bounds__(128)
void proj_kernel(const float* __restrict__ Wp,
                 const float* __restrict__ bp,
                 const float* __restrict__ skip,
                 float* __restrict__ out)
{
    __shared__ float ab[8][128];
    const int tid   = threadIdx.x;
    const int obase = blockIdx.x * 8;

    #pragma unroll
    for (int t = 0; t < 4; t++) {
        const int idx = tid + t * 128;
        const int r   = idx >> 6;
        const int cp  = idx & 63;
        const int o   = obase + r;
        const int L   = o >> 6;
        const int wi  = o & 63;
        float sx = 0.f, sy = 0.f;
        #pragma unroll
        for (int n = 0; n < 6; n++) {
            const u32 hv = *(const u32*)(g_att16 + (L * 384 + n * 64 + wi) * D + cp * 2);
            const float2 f = __half22float2(*(const __half2*)&hv);
            sx += f.x; sy += f.y;
        }
        ab[r][cp * 2]     = sx * (1.0f / 6.0f);
        ab[r][cp * 2 + 1] = sy * (1.0f / 6.0f);
    }
    __syncthreads();

    const int c = tid;
    float acc[8];
    const float bb = bp[c];
    #pragma unroll
    for (int r = 0; r < 8; r++) acc[r] = bb;

    #pragma unroll 8
    for (int j = 0; j < 128; j++) {
        const float w = Wp[j * 128 + c];
        #pragma unroll
        for (int r = 0; r < 8; r++) acc[r] = fmaf(ab[r][j], w, acc[r]);
    }
    #pragma unroll
    for (int r = 0; r < 8; r++) {
        const int o = obase + r;
        out[o * D + c] = acc[r] + skip[o * D + c];
    }
}

// ---------------------------------------------------------------------------
extern "C" void kernel_launch(void* const* d_in, const int* in_sizes, int n_in,
                              void* d_out, int out_size)
{
    const float* q          = (const float*)d_in[0];
    const float* k          = (const float*)d_in[1];
    const float* v          = (const float*)d_in[2];
    const float* skip       = (const float*)d_in[3];
    const float* attn_scale = (const float*)d_in[4];
    const float* lnq_g = (const float*)d_in[5];
    const float* lnq_b = (const float*)d_in[6];
    const float* Wq    = (const float*)d_in[7];
    const float* bq    = (const float*)d_in[8];
    const float* lnk_g = (const float*)d_in[9];
    const float* lnk_b = (const float*)d_in[10];
    const float* Wk    = (const float*)d_in[11];
    const float* bk    = (const float*)d_in[12];
    const float* lnv_g = (const float*)d_in[13];
    const float* lnv_b = (const float*)d_in[14];
    const float* Wv    = (const float*)d_in[15];
    const float* bv    = (const float*)d_in[16];
    const float* Wp    = (const float*)d_in[17];
    const float* bp    = (const float*)d_in[18];
    float* out = (float*)d_out;

    static int smem_set = 0;
    if (!smem_set) {
        cudaFuncSetAttribute(ln_all_kernel,
                             cudaFuncAttributeMaxDynamicSharedMemorySize,
                             LN_SMEM_BYTES);
        smem_set = 1;
    }

    ln_all_kernel<<<1344, 128, LN_SMEM_BYTES>>>(q, k, v, attn_scale,
                                                lnq_g, lnq_b, Wq, bq,
                                                lnk_g, lnk_b, Wk, bk,
                                                lnv_g, lnv_b, Wv, bv);

    attn_kernel<<<768, 128>>>(attn_scale);

    proj_kernel<<<4096 / 8, 128>>>(Wp, bp, skip, out);
}